// round 7
// baseline (speedup 1.0000x reference)
#include <cuda_runtime.h>
#include <math.h>
#include <stdint.h>

#define BB   2
#define NN   768
#define TT   96
#define FMF  8
#define HIDD 64
#define TDD  32

#define NTILE 24           // 768/32
#define NUPPER 300         // 24*25/2
#define TOTTILES (NUPPER * BB)
#define GRIDP 592          // 148 SMs * 2 CTAs, one wave slot count
#define PAD 68             // word-pad so (4*row + col) & 31 is lane-unique

// ---------------------------------------------------------------------------
// helpers
// ---------------------------------------------------------------------------
__device__ __forceinline__ uint32_t f2tf32(float f) {
    uint32_t r; asm("cvt.rna.tf32.f32 %0, %1;" : "=r"(r) : "f"(f)); return r;
}

__device__ __forceinline__ void mma_tf32(float* d,
                                         uint32_t a0, uint32_t a1, uint32_t a2, uint32_t a3,
                                         uint32_t b0, uint32_t b1) {
    asm volatile(
        "mma.sync.aligned.m16n8k8.row.col.f32.tf32.tf32.f32 "
        "{%0,%1,%2,%3}, {%4,%5,%6,%7}, {%8,%9}, {%0,%1,%2,%3};"
        : "+f"(d[0]), "+f"(d[1]), "+f"(d[2]), "+f"(d[3])
        : "r"(a0), "r"(a1), "r"(a2), "r"(a3), "r"(b0), "r"(b1));
}

// Scratch (allocation-free rule: __device__ globals)
__device__ float g_h[BB * NN * HIDD];
__device__ float g_P[BB * NN * HIDD];   // h @ w_i + ps_b1
__device__ float g_Q[BB * NN * HIDD];   // h @ w_j

// ---------------------------------------------------------------------------
// Kernel 1: per-node features. One node per warp; 8 warps/block. All weights
// staged ONCE per block into smem (coalesced), then LDS-only MLP chain.
// ---------------------------------------------------------------------------
// smem float offsets
#define O_TE1   0                    // 96
#define O_TB1   (O_TE1 + 96)         // 32
#define O_ME1   (O_TB1 + 32)         // 256
#define O_MB1   (O_ME1 + 256)        // 32
#define O_TE2   (O_MB1 + 32)         // 1024
#define O_TB2   (O_TE2 + 1024)       // 32
#define O_ME2   (O_TB2 + 32)         // 1024
#define O_MB2   (O_ME2 + 1024)       // 32
#define O_NFW   (O_MB2 + 32)         // 4096
#define O_NFB   (O_NFW + 4096)       // 64
#define O_WI    (O_NFB + 64)         // 4096
#define O_WJ    (O_WI + 4096)        // 4096
#define O_PB1   (O_WJ + 4096)        // 64
#define NODE_SM_FLOATS (O_PB1 + 64)
#define NODE_SM_BYTES (NODE_SM_FLOATS * 4)

__global__ __launch_bounds__(256)
void node_kernel(const float* __restrict__ x_hist, const float* __restrict__ x_mark,
                 const float* __restrict__ te_w1, const float* __restrict__ te_b1,
                 const float* __restrict__ te_w2, const float* __restrict__ te_b2,
                 const float* __restrict__ me_w1, const float* __restrict__ me_b1,
                 const float* __restrict__ me_w2, const float* __restrict__ me_b2,
                 const float* __restrict__ nf_w,  const float* __restrict__ nf_b,
                 const float* __restrict__ ps_w1, const float* __restrict__ ps_b1)
{
    extern __shared__ float sw[];
    const int tid  = threadIdx.x;
    const int lane = tid & 31;
    const int node = blockIdx.x * 8 + (tid >> 5);

    // ---- stage all weights into smem (coalesced, high MLP) ----
    for (int e = tid; e < 96;   e += 256) sw[O_TE1 + e] = te_w1[e];
    for (int e = tid; e < 32;   e += 256) { sw[O_TB1 + e] = te_b1[e];
                                            sw[O_MB1 + e] = me_b1[e];
                                            sw[O_TB2 + e] = te_b2[e];
                                            sw[O_MB2 + e] = me_b2[e]; }
    for (int e = tid; e < 256;  e += 256) sw[O_ME1 + e] = me_w1[e];
    for (int e = tid; e < 1024; e += 256) { sw[O_TE2 + e] = te_w2[e];
                                            sw[O_ME2 + e] = me_w2[e]; }
    for (int e = tid; e < 4096; e += 256) { sw[O_NFW + e] = nf_w[e];
                                            sw[O_WI  + e] = ps_w1[e];
                                            sw[O_WJ  + e] = ps_w1[HIDD * HIDD + e]; }
    for (int e = tid; e < 64;   e += 256) { sw[O_NFB + e] = nf_b[e];
                                            sw[O_PB1 + e] = ps_b1[e]; }
    __syncthreads();

    const float* xh = x_hist + (size_t)node * TT;
    const float* xm = x_mark + (size_t)node * TT * FMF;

    // ---- stats over T = 96 = 3*32 ----
    float v0 = xh[lane], v1 = xh[lane + 32], v2 = xh[lane + 64];
    float s  = v0 + v1 + v2;
    float mx = fmaxf(v0, fmaxf(v1, v2));
    #pragma unroll
    for (int off = 16; off > 0; off >>= 1) {
        s  += __shfl_xor_sync(0xFFFFFFFF, s, off);
        mx  = fmaxf(mx, __shfl_xor_sync(0xFFFFFFFF, mx, off));
    }
    const float st0 = __shfl_sync(0xFFFFFFFF, v2, 31);   // xh[95]
    const float st1 = s * (1.f / (float)TT);
    const float st2 = mx;

    // ---- mark mean: 768 = 32*24 coalesced; lane l accumulates feature l&7 ----
    float ms = 0.f;
    #pragma unroll
    for (int q = 0; q < 24; q++) ms += xm[lane + 32 * q];
    ms += __shfl_xor_sync(0xFFFFFFFF, ms, 8);
    ms += __shfl_xor_sync(0xFFFFFFFF, ms, 16);
    ms *= (1.f / (float)TT);          // lane l holds msum[l & 7]

    // ---- layer 1 ----
    float t1 = sw[O_TB1 + lane];
    t1 = fmaf(st0, sw[O_TE1 + lane], t1);
    t1 = fmaf(st1, sw[O_TE1 + 32 + lane], t1);
    t1 = fmaf(st2, sw[O_TE1 + 64 + lane], t1);
    t1 = fmaxf(t1, 0.f);

    float m1 = sw[O_MB1 + lane];
    #pragma unroll
    for (int c = 0; c < FMF; c++)
        m1 = fmaf(__shfl_sync(0xFFFFFFFF, ms, c), sw[O_ME1 + c * TDD + lane], m1);
    m1 = fmaxf(m1, 0.f);

    // ---- layer 2 ----
    float t2 = sw[O_TB2 + lane], m2 = sw[O_MB2 + lane];
    #pragma unroll
    for (int c = 0; c < TDD; c++) {
        t2 = fmaf(__shfl_sync(0xFFFFFFFF, t1, c), sw[O_TE2 + c * TDD + lane], t2);
        m2 = fmaf(__shfl_sync(0xFFFFFFFF, m1, c), sw[O_ME2 + c * TDD + lane], m2);
    }

    // ---- node fuse: h[2*lane], h[2*lane+1] ----
    const int k0 = 2 * lane;
    float2 hb = *(const float2*)&sw[O_NFB + k0];
    float h0 = hb.x, h1 = hb.y;
    #pragma unroll
    for (int c = 0; c < TDD; c++) {
        float hc = __shfl_sync(0xFFFFFFFF, t2, c);
        float2 wv = *(const float2*)&sw[O_NFW + c * HIDD + k0];
        h0 = fmaf(hc, wv.x, h0); h1 = fmaf(hc, wv.y, h1);
    }
    #pragma unroll
    for (int c = 0; c < TDD; c++) {
        float hc = __shfl_sync(0xFFFFFFFF, m2, c);
        float2 wv = *(const float2*)&sw[O_NFW + (TDD + c) * HIDD + k0];
        h0 = fmaf(hc, wv.x, h0); h1 = fmaf(hc, wv.y, h1);
    }
    h0 = fmaxf(h0, 0.f); h1 = fmaxf(h1, 0.f);
    *(float2*)&g_h[(size_t)node * HIDD + k0] = make_float2(h0, h1);

    // ---- P = h@w_i + ps_b1, Q = h@w_j ----
    float2 pb = *(const float2*)&sw[O_PB1 + k0];
    float p0 = pb.x, p1 = pb.y, q0 = 0.f, q1 = 0.f;
    #pragma unroll
    for (int cc = 0; cc < TDD; cc++) {
        float ha  = __shfl_sync(0xFFFFFFFF, h0, cc);   // h[2cc]
        float hbv = __shfl_sync(0xFFFFFFFF, h1, cc);   // h[2cc+1]
        float2 wiA = *(const float2*)&sw[O_WI + (2 * cc) * HIDD + k0];
        float2 wiB = *(const float2*)&sw[O_WI + (2 * cc + 1) * HIDD + k0];
        float2 wjA = *(const float2*)&sw[O_WJ + (2 * cc) * HIDD + k0];
        float2 wjB = *(const float2*)&sw[O_WJ + (2 * cc + 1) * HIDD + k0];
        p0 = fmaf(ha, wiA.x, p0); p1 = fmaf(ha, wiA.y, p1);
        p0 = fmaf(hbv, wiB.x, p0); p1 = fmaf(hbv, wiB.y, p1);
        q0 = fmaf(ha, wjA.x, q0); q1 = fmaf(ha, wjA.y, q1);
        q0 = fmaf(hbv, wjB.x, q0); q1 = fmaf(hbv, wjB.y, q1);
    }
    *(float2*)&g_P[(size_t)node * HIDD + k0] = make_float2(p0, p1);
    *(float2*)&g_Q[(size_t)node * HIDD + k0] = make_float2(q0, q1);
}

// ---------------------------------------------------------------------------
// Kernel 2: pairwise delta via tf32 mma.sync. Persistent grid of 592 blocks.
// ---------------------------------------------------------------------------
#define BF_BYTES (8 * 4 * 32 * 16)                   // uint4 table, 16 KB
#define SM_BYTES (BF_BYTES + (6 * 32 * PAD + 64) * 4)

__global__ __launch_bounds__(256, 2)
void pair_kernel(const float* __restrict__ ps_w1, const float* __restrict__ ps_w2,
                 const float* __restrict__ ps_b2, float* __restrict__ out)
{
    extern __shared__ __align__(16) char smx[];
    uint4* Bq = (uint4*)smx;                         // [kt][ntp][lane]
    float* fp = (float*)(smx + BF_BYTES);
    float* hI  = fp;                                 // [32][PAD]
    float* hJ  = hI + 32 * PAD;
    float* PI  = hJ + 32 * PAD;
    float* QI  = PI + 32 * PAD;
    float* PJ  = QI + 32 * PAD;
    float* QJ  = PJ + 32 * PAD;
    float* w2s = QJ + 32 * PAD;                      // [64]

    const int tid  = threadIdx.x;
    const int w    = tid >> 5;
    const int lane = tid & 31;
    const int gid  = lane >> 2;                      // 0..7
    const int tig  = lane & 3;                       // 0..3

    // B fragment table (uint4), tile-independent: load once.
    for (int e = tid; e < 8 * 4 * 32; e += 256) {
        int ktp = e >> 5, ln = e & 31;
        int kt = ktp >> 2, ntp = ktp & 3;
        int gd = ln >> 2, tg = ln & 3;
        int c0 = kt * 8 + tg;
        int n0 = (2 * ntp) * 8 + gd, n1 = (2 * ntp + 1) * 8 + gd;
        uint4 v;
        v.x = f2tf32(ps_w1[(128 + c0) * HIDD + n0]);
        v.y = f2tf32(ps_w1[(128 + c0 + 4) * HIDD + n0]);
        v.z = f2tf32(ps_w1[(128 + c0) * HIDD + n1]);
        v.w = f2tf32(ps_w1[(128 + c0 + 4) * HIDD + n1]);
        Bq[(size_t)ktp * 32 + ln] = v;
    }
    if (tid < 64) w2s[tid] = ps_w2[tid];
    const float b2v = ps_b2[0];

    #pragma unroll 1
    for (int t = blockIdx.x; t < TOTTILES; t += GRIDP) {
        const int b = t / NUPPER;
        int u = t - b * NUPPER, ti = 0;
        while (u >= NTILE - ti) { u -= NTILE - ti; ti++; }
        const int tj = ti + u;

        const int baseI = (b * NN + ti * 32) * HIDD;
        const int baseJ = (b * NN + tj * 32) * HIDD;

        __syncthreads();   // prior iteration's reads done (and Bq ready, iter 0)
        for (int e = tid; e < 32 * HIDD; e += 256) {
            int r = e >> 6, c = e & 63;
            hI[r * PAD + c] = g_h[baseI + e];
            hJ[r * PAD + c] = g_h[baseJ + e];
            PI[r * PAD + c] = g_P[baseI + e];
            QI[r * PAD + c] = g_Q[baseI + e];
            PJ[r * PAD + c] = g_P[baseJ + e];
            QJ[r * PAD + c] = g_Q[baseJ + e];
        }
        __syncthreads();

        float* ob = out + (size_t)b * NN * NN;

        #pragma unroll 1
        for (int it = 0; it < 4; it++) {
            const int i  = it * 8 + w;               // warp-uniform tile row
            const int iP = i * PAD;

            float acc[2][8][4];
            #pragma unroll
            for (int mt = 0; mt < 2; mt++)
                #pragma unroll
                for (int n = 0; n < 8; n++)
                    #pragma unroll
                    for (int x = 0; x < 4; x++) acc[mt][n][x] = 0.f;

            const int r0 = gid * PAD, r1 = (gid + 8) * PAD,
                      r2 = (gid + 16) * PAD, r3 = (gid + 24) * PAD;

            #pragma unroll
            for (int kt = 0; kt < 8; kt++) {
                const int c0 = kt * 8 + tig, c1 = c0 + 4;
                const float hi0 = hI[iP + c0], hi1 = hI[iP + c1];
                uint32_t A00 = f2tf32(fabsf(hi0 - hJ[r0 + c0]));
                uint32_t A01 = f2tf32(fabsf(hi0 - hJ[r1 + c0]));
                uint32_t A02 = f2tf32(fabsf(hi1 - hJ[r0 + c1]));
                uint32_t A03 = f2tf32(fabsf(hi1 - hJ[r1 + c1]));
                uint32_t A10 = f2tf32(fabsf(hi0 - hJ[r2 + c0]));
                uint32_t A11 = f2tf32(fabsf(hi0 - hJ[r3 + c0]));
                uint32_t A12 = f2tf32(fabsf(hi1 - hJ[r2 + c1]));
                uint32_t A13 = f2tf32(fabsf(hi1 - hJ[r3 + c1]));
                #pragma unroll
                for (int ntp = 0; ntp < 4; ntp++) {
                    uint4 bv = Bq[(size_t)(kt * 4 + ntp) * 32 + lane];
                    mma_tf32(acc[0][2 * ntp],     A00, A01, A02, A03, bv.x, bv.y);
                    mma_tf32(acc[1][2 * ntp],     A10, A11, A12, A13, bv.x, bv.y);
                    mma_tf32(acc[0][2 * ntp + 1], A00, A01, A02, A03, bv.z, bv.w);
                    mma_tf32(acc[1][2 * ntp + 1], A10, A11, A12, A13, bv.z, bv.w);
                }
            }

            // epilogue
            float sij[4], sji[4];
            #pragma unroll
            for (int rr = 0; rr < 4; rr++) { sij[rr] = 0.f; sji[rr] = 0.f; }

            #pragma unroll
            for (int nt = 0; nt < 8; nt++) {
                const int k0 = nt * 8 + tig * 2;
                const float2 piv = *(const float2*)&PI[iP + k0];
                const float2 qiv = *(const float2*)&QI[iP + k0];
                const float2 w2v = *(const float2*)&w2s[k0];
                #pragma unroll
                for (int rr = 0; rr < 4; rr++) {
                    const int row = gid + 8 * rr;
                    const float dk0 = acc[rr >> 1][nt][(rr & 1) * 2];
                    const float dk1 = acc[rr >> 1][nt][(rr & 1) * 2 + 1];
                    const float2 qjv = *(const float2*)&QJ[row * PAD + k0];
                    const float2 pjv = *(const float2*)&PJ[row * PAD + k0];
                    sij[rr] = fmaf(fmaxf(dk0 + piv.x + qjv.x, 0.f), w2v.x, sij[rr]);
                    sij[rr] = fmaf(fmaxf(dk1 + piv.y + qjv.y, 0.f), w2v.y, sij[rr]);
                    sji[rr] = fmaf(fmaxf(dk0 + pjv.x + qiv.x, 0.f), w2v.x, sji[rr]);
                    sji[rr] = fmaf(fmaxf(dk1 + pjv.y + qiv.y, 0.f), w2v.y, sji[rr]);
                }
            }

            // quad reduction; bias added once after
            #pragma unroll
            for (int rr = 0; rr < 4; rr++) {
                sij[rr] += __shfl_xor_sync(0xFFFFFFFF, sij[rr], 1);
                sij[rr] += __shfl_xor_sync(0xFFFFFFFF, sij[rr], 2);
                sji[rr] += __shfl_xor_sync(0xFFFFFFFF, sji[rr], 1);
                sji[rr] += __shfl_xor_sync(0xFFFFFFFF, sji[rr], 2);
            }

            const int j  = gid + 8 * tig;
            const int gi = ti * 32 + i, gj = tj * 32 + j;
            const float a_ij = sij[tig] + b2v;
            const float a_ji = sji[tig] + b2v;
            if (ti != tj || i < j) {
                float d = 0.5f * (tanhf(a_ij) + tanhf(a_ji));
                ob[(size_t)gi * NN + gj] = d;
                ob[(size_t)gj * NN + gi] = d;
            } else if (i == j) {
                ob[(size_t)gi * NN + gj] = 0.f;
            }
        }
    }
}

// ---------------------------------------------------------------------------
// Kernel 3: a = relu(a_static + lam*delta); row-normalize; write lam.
// ---------------------------------------------------------------------------
__global__ __launch_bounds__(256)
void finalize_kernel(const float* __restrict__ a_static,
                     const float* __restrict__ raw_lambda,
                     float* __restrict__ out, int out_size)
{
    const int row = blockIdx.x;
    const int b = row / NN, i = row % NN;
    const int tid = threadIdx.x;

    const float lam = 1.f / (1.f + expf(-raw_lambda[0]));
    float* orow = out + ((size_t)b * NN + i) * NN;
    const float* arow = a_static + (size_t)i * NN;

    float v[3];
    float s = 0.f;
    #pragma unroll
    for (int r = 0; r < 3; r++) {
        int j = tid + 256 * r;
        float a = fmaxf(fmaf(lam, orow[j], arow[j]), 0.f);
        v[r] = a;
        s += a;
    }

    __shared__ float red[256];
    red[tid] = s;
    __syncthreads();
    for (int off = 128; off > 0; off >>= 1) {
        if (tid < off) red[tid] += red[tid + off];
        __syncthreads();
    }
    float inv = 1.f / fmaxf(red[0], 1e-6f);
    #pragma unroll
    for (int r = 0; r < 3; r++) orow[tid + 256 * r] = v[r] * inv;

    if (row == 0 && tid == 0) {
        for (int idx = BB * NN * NN; idx < out_size; idx++) out[idx] = lam;
    }
}

// ---------------------------------------------------------------------------
extern "C" void kernel_launch(void* const* d_in, const int* in_sizes, int n_in,
                              void* d_out, int out_size)
{
    const float* x_hist   = (const float*)d_in[0];
    const float* x_mark   = (const float*)d_in[1];
    const float* a_static = (const float*)d_in[2];
    const float* te_w1 = (const float*)d_in[3];
    const float* te_b1 = (const float*)d_in[4];
    const float* te_w2 = (const float*)d_in[5];
    const float* te_b2 = (const float*)d_in[6];
    const float* me_w1 = (const float*)d_in[7];
    const float* me_b1 = (const float*)d_in[8];
    const float* me_w2 = (const float*)d_in[9];
    const float* me_b2 = (const float*)d_in[10];
    const float* nf_w  = (const float*)d_in[11];
    const float* nf_b  = (const float*)d_in[12];
    const float* ps_w1 = (const float*)d_in[13];
    const float* ps_b1 = (const float*)d_in[14];
    const float* ps_w2 = (const float*)d_in[15];
    const float* ps_b2 = (const float*)d_in[16];
    const float* raw_lambda = (const float*)d_in[17];
    float* out = (float*)d_out;

    static bool attr_set = false;
    if (!attr_set) {
        cudaFuncSetAttribute(pair_kernel,
                             cudaFuncAttributeMaxDynamicSharedMemorySize, SM_BYTES);
        cudaFuncSetAttribute(node_kernel,
                             cudaFuncAttributeMaxDynamicSharedMemorySize, NODE_SM_BYTES);
        attr_set = true;
    }

    node_kernel<<<BB * NN / 8, 256, NODE_SM_BYTES>>>(
        x_hist, x_mark, te_w1, te_b1, te_w2, te_b2,
        me_w1, me_b1, me_w2, me_b2, nf_w, nf_b, ps_w1, ps_b1);

    pair_kernel<<<GRIDP, 256, SM_BYTES>>>(ps_w1, ps_w2, ps_b2, out);

    finalize_kernel<<<BB * NN, 256>>>(a_static, raw_lambda, out, out_size);
}